// round 4
// baseline (speedup 1.0000x reference)
#include <cuda_runtime.h>
#include <math.h>

#define B_ 8
#define C_ 128
#define N_ 2048
#define H_ 4
#define K_ 32
#define D_ 32
#define F_ 512
#define P_ (B_*N_)
#define EPSbn 1e-5f

// ---------------- scratch (static device allocations only) ----------------
__device__ float g_S[B_*N_*N_];        // 128MB scores; later reused for FFN hidden h (float)
__device__ int   g_idx[P_*K_];
__device__ float g_xq[P_*C_];
__device__ float g_xk[P_*C_];
__device__ float g_xv[P_*C_];
__device__ float g_x2[P_];
__device__ float g_s1[P_*C_];
__device__ float g_x1[P_*C_];
__device__ float g_s2[P_*C_];
__device__ float g_sum1[2*C_];
__device__ float g_sum2[2*C_];
__device__ float g_stat1[2*C_];
__device__ float g_stat2[2*C_];
__device__ unsigned g_wqT[C_*C_],  g_wqTl[C_*C_];   // [cin][cout] tf32 hi/lo bits
__device__ unsigned g_wkT[C_*C_],  g_wkTl[C_*C_];
__device__ unsigned g_wvT[C_*C_],  g_wvTl[C_*C_];
__device__ unsigned g_w1T[C_*F_],  g_w1Tl[C_*F_];   // [cin][o]
__device__ unsigned g_w2T[F_*C_],  g_w2Tl[F_*C_];   // [o][cout]

__device__ __forceinline__ unsigned f2tf(float v) {
    unsigned u; asm("cvt.rna.tf32.f32 %0, %1;" : "=r"(u) : "f"(v)); return u;
}
__device__ __forceinline__ void split_tf(float v, unsigned& hi, unsigned& lo) {
    hi = f2tf(v);
    lo = f2tf(v - __uint_as_float(hi));
}
__device__ __forceinline__ void mma_tf32(float* c, const unsigned* a, const unsigned* b) {
    asm volatile("mma.sync.aligned.m16n8k8.row.col.f32.tf32.tf32.f32 "
        "{%0,%1,%2,%3}, {%4,%5,%6,%7}, {%8,%9}, {%0,%1,%2,%3};"
        : "+f"(c[0]), "+f"(c[1]), "+f"(c[2]), "+f"(c[3])
        : "r"(a[0]), "r"(a[1]), "r"(a[2]), "r"(a[3]), "r"(b[0]), "r"(b[1]));
}

// fragment load + 3xTF32 mma block, shared by all GEMM kernels.
// smem layout [8][136], warp tile 64x32 (warpM half, warpN quarter).
#define FRAG_AND_MMA(AH, AL, BH, BL)                                          \
    unsigned a_hi[4][4], a_lo[4][4], b_hi[4][2], b_lo[4][2];                  \
    _Pragma("unroll")                                                         \
    for (int mt = 0; mt < 4; mt++) {                                          \
        int mb = warpM*64 + mt*16 + g;                                        \
        a_hi[mt][0] = AH[tid4][mb];    a_hi[mt][1] = AH[tid4][mb+8];          \
        a_hi[mt][2] = AH[tid4+4][mb];  a_hi[mt][3] = AH[tid4+4][mb+8];        \
        a_lo[mt][0] = AL[tid4][mb];    a_lo[mt][1] = AL[tid4][mb+8];          \
        a_lo[mt][2] = AL[tid4+4][mb];  a_lo[mt][3] = AL[tid4+4][mb+8];        \
    }                                                                         \
    _Pragma("unroll")                                                         \
    for (int nt = 0; nt < 4; nt++) {                                          \
        int nb = warpN*32 + nt*8 + g;                                         \
        b_hi[nt][0] = BH[tid4][nb];    b_hi[nt][1] = BH[tid4+4][nb];          \
        b_lo[nt][0] = BL[tid4][nb];    b_lo[nt][1] = BL[tid4+4][nb];          \
    }                                                                         \
    _Pragma("unroll")                                                         \
    for (int mt = 0; mt < 4; mt++)                                            \
        _Pragma("unroll")                                                     \
        for (int nt = 0; nt < 4; nt++) {                                      \
            mma_tf32(acc[mt][nt], a_hi[mt], b_lo[nt]);                        \
            mma_tf32(acc[mt][nt], a_lo[mt], b_hi[nt]);                        \
            mma_tf32(acc[mt][nt], a_hi[mt], b_hi[nt]);                        \
        }

// ---------------- init ----------------
__global__ void init_kernel() {
    int t = threadIdx.x;
    if (t < 2*C_) { g_sum1[t] = 0.f; g_sum2[t] = 0.f; }
}

// ---------------- transpose + tf32 split weights: dst[c*R + r] = src[r*Cc + c]
__global__ void tp_kernel(const float* __restrict__ src, unsigned* __restrict__ dh,
                          unsigned* __restrict__ dl, int R, int Cc) {
    int i = blockIdx.x*256 + threadIdx.x;
    if (i >= R*Cc) return;
    int r = i / Cc, c = i % Cc;
    unsigned hi, lo; split_tf(src[i], hi, lo);
    dh[(size_t)c*R + r] = hi;
    dl[(size_t)c*R + r] = lo;
}

// ---------------- per-point squared norms ----------------
__global__ void colnorm_kernel(const float* __restrict__ x) {
    int p = blockIdx.x*blockDim.x + threadIdx.x;
    if (p >= P_) return;
    int b = p / N_, n = p % N_;
    const float* xb = x + (size_t)b*C_*N_ + n;
    float s = 0.f;
    #pragma unroll
    for (int c = 0; c < C_; c++) { float v = xb[(size_t)c*N_]; s += v*v; }
    g_x2[p] = s;
}

// ---------------- score GEMM (3xTF32): S[n,m] = dot - 0.5*||x_m||^2, symmetric ----
__global__ __launch_bounds__(256) void score_tc(const float* __restrict__ x) {
    const int T = 16;
    int L = blockIdx.x;
    int i = 0, rem = L;
    while (rem >= T - i) { rem -= (T - i); i++; }
    int j = i + rem;
    int n0 = i*128, m0 = j*128;
    int b = blockIdx.z;
    const float* xb  = x + (size_t)b*C_*N_;
    float* Sb        = g_S + (size_t)b*N_*N_;
    const float* x2b = g_x2 + b*N_;

    __shared__ unsigned Ah[8][136], Al[8][136], Bh[8][136], Bl[8][136];
    int t = threadIdx.x, lane = t & 31, wid = t >> 5;
    int warpM = wid >> 2, warpN = wid & 3;
    int g = lane >> 2, tid4 = lane & 3;
    float acc[4][4][4];
    #pragma unroll
    for (int a = 0; a < 4; a++)
        #pragma unroll
        for (int c = 0; c < 4; c++)
            #pragma unroll
            for (int e = 0; e < 4; e++) acc[a][c][e] = 0.f;

    for (int kc = 0; kc < C_; kc += 8) {
        #pragma unroll
        for (int q = 0; q < 4; q++) {
            int e = t + q*256;
            int kk = e >> 7, nn = e & 127;
            unsigned hi, lo;
            split_tf(xb[(size_t)(kc+kk)*N_ + n0 + nn], hi, lo);
            Ah[kk][nn] = hi; Al[kk][nn] = lo;
            split_tf(xb[(size_t)(kc+kk)*N_ + m0 + nn], hi, lo);
            Bh[kk][nn] = hi; Bl[kk][nn] = lo;
        }
        __syncthreads();
        FRAG_AND_MMA(Ah, Al, Bh, Bl)
        __syncthreads();
    }
    #pragma unroll
    for (int mt = 0; mt < 4; mt++) {
        int r0 = n0 + warpM*64 + mt*16 + g;
        int r1 = r0 + 8;
        float xr0 = x2b[r0], xr1 = x2b[r1];
        #pragma unroll
        for (int nt = 0; nt < 4; nt++) {
            int c0 = m0 + warpN*32 + nt*8 + 2*tid4;
            float* A4 = acc[mt][nt];
            float h0 = 0.5f*x2b[c0], h1 = 0.5f*x2b[c0+1];
            *(float2*)&Sb[(size_t)r0*N_ + c0] = make_float2(A4[0]-h0, A4[1]-h1);
            *(float2*)&Sb[(size_t)r1*N_ + c0] = make_float2(A4[2]-h0, A4[3]-h1);
            if (i != j) {
                Sb[(size_t)c0*N_ + r0]     = A4[0] - 0.5f*xr0;
                Sb[(size_t)(c0+1)*N_ + r0] = A4[1] - 0.5f*xr0;
                Sb[(size_t)c0*N_ + r1]     = A4[2] - 0.5f*xr1;
                Sb[(size_t)(c0+1)*N_ + r1] = A4[3] - 0.5f*xr1;
            }
        }
    }
}

// ---------------- q/k/v projections (3xTF32): out[p][o] = sum_c x[b,c,n] wT[c][o]
__global__ __launch_bounds__(256) void proj_tc(const float* __restrict__ x) {
    int n0 = blockIdx.x*128;
    int widx = blockIdx.y;
    int b = blockIdx.z;
    const float* xb = x + (size_t)b*C_*N_;
    const unsigned* wT  = widx == 0 ? g_wqT  : (widx == 1 ? g_wkT  : g_wvT);
    const unsigned* wTl = widx == 0 ? g_wqTl : (widx == 1 ? g_wkTl : g_wvTl);
    float* outp = (widx == 0 ? g_xq : widx == 1 ? g_xk : g_xv) + (size_t)b*N_*C_;

    __shared__ unsigned Ah[8][136], Al[8][136], Bh[8][136], Bl[8][136];
    int t = threadIdx.x, lane = t & 31, wid = t >> 5;
    int warpM = wid >> 2, warpN = wid & 3;
    int g = lane >> 2, tid4 = lane & 3;
    float acc[4][4][4];
    #pragma unroll
    for (int a = 0; a < 4; a++)
        #pragma unroll
        for (int c = 0; c < 4; c++)
            #pragma unroll
            for (int e = 0; e < 4; e++) acc[a][c][e] = 0.f;

    for (int kc = 0; kc < C_; kc += 8) {
        #pragma unroll
        for (int q = 0; q < 4; q++) {
            int e = t + q*256;
            int kk = e >> 7, nn = e & 127;
            unsigned hi, lo;
            split_tf(xb[(size_t)(kc+kk)*N_ + n0 + nn], hi, lo);
            Ah[kk][nn] = hi; Al[kk][nn] = lo;
            Bh[kk][nn] = wT [(size_t)(kc+kk)*C_ + nn];
            Bl[kk][nn] = wTl[(size_t)(kc+kk)*C_ + nn];
        }
        __syncthreads();
        FRAG_AND_MMA(Ah, Al, Bh, Bl)
        __syncthreads();
    }
    #pragma unroll
    for (int mt = 0; mt < 4; mt++) {
        int r0 = n0 + warpM*64 + mt*16 + g;
        #pragma unroll
        for (int nt = 0; nt < 4; nt++) {
            int c0 = warpN*32 + nt*8 + 2*tid4;
            float* A4 = acc[mt][nt];
            *(float2*)&outp[(size_t)r0*C_ + c0]     = make_float2(A4[0], A4[1]);
            *(float2*)&outp[(size_t)(r0+8)*C_ + c0] = make_float2(A4[2], A4[3]);
        }
    }
}

// ---------------- FFN gemm1 (3xTF32): h[p][o] = leaky(sum_c x1[p][c] w1T[c][o])
__global__ __launch_bounds__(256) void ffn1_tc() {
    int o0 = blockIdx.x*128;
    int p0 = blockIdx.y*128;
    float* hb = g_S;

    __shared__ unsigned Ah[8][136], Al[8][136], Bh[8][136], Bl[8][136];
    int t = threadIdx.x, lane = t & 31, wid = t >> 5;
    int warpM = wid >> 2, warpN = wid & 3;
    int g = lane >> 2, tid4 = lane & 3;
    float acc[4][4][4];
    #pragma unroll
    for (int a = 0; a < 4; a++)
        #pragma unroll
        for (int c = 0; c < 4; c++)
            #pragma unroll
            for (int e = 0; e < 4; e++) acc[a][c][e] = 0.f;

    for (int kc = 0; kc < C_; kc += 8) {
        #pragma unroll
        for (int q = 0; q < 4; q++) {
            int e = t + q*256;
            int pm = e >> 3, kk = e & 7;
            unsigned hi, lo;
            split_tf(g_x1[(size_t)(p0+pm)*C_ + kc + kk], hi, lo);
            Ah[kk][pm] = hi; Al[kk][pm] = lo;
            int kk2 = e >> 7, nn = e & 127;
            Bh[kk2][nn] = g_w1T [(size_t)(kc+kk2)*F_ + o0 + nn];
            Bl[kk2][nn] = g_w1Tl[(size_t)(kc+kk2)*F_ + o0 + nn];
        }
        __syncthreads();
        FRAG_AND_MMA(Ah, Al, Bh, Bl)
        __syncthreads();
    }
    #pragma unroll
    for (int mt = 0; mt < 4; mt++) {
        int r0 = p0 + warpM*64 + mt*16 + g;
        #pragma unroll
        for (int nt = 0; nt < 4; nt++) {
            int c0 = o0 + warpN*32 + nt*8 + 2*tid4;
            float* A4 = acc[mt][nt];
            #pragma unroll
            for (int e = 0; e < 4; e++) A4[e] = A4[e] > 0.f ? A4[e] : 0.2f*A4[e];
            *(float2*)&hb[(size_t)r0*F_ + c0]     = make_float2(A4[0], A4[1]);
            *(float2*)&hb[(size_t)(r0+8)*F_ + c0] = make_float2(A4[2], A4[3]);
        }
    }
}

// ---------------- FFN gemm2 (3xTF32): s2[p][c] = x1 + sum_o h[p][o] w2T[o][c]
__global__ __launch_bounds__(256) void ffn2_tc() {
    int p0 = blockIdx.y*128;
    const float* hb = g_S;

    __shared__ unsigned Ah[8][136], Al[8][136], Bh[8][136], Bl[8][136];
    int t = threadIdx.x, lane = t & 31, wid = t >> 5;
    int warpM = wid >> 2, warpN = wid & 3;
    int g = lane >> 2, tid4 = lane & 3;
    float acc[4][4][4];
    #pragma unroll
    for (int a = 0; a < 4; a++)
        #pragma unroll
        for (int c = 0; c < 4; c++)
            #pragma unroll
            for (int e = 0; e < 4; e++) acc[a][c][e] = 0.f;

    for (int kc = 0; kc < F_; kc += 8) {
        #pragma unroll
        for (int q = 0; q < 4; q++) {
            int e = t + q*256;
            int pm = e >> 3, kk = e & 7;
            unsigned hi, lo;
            split_tf(hb[(size_t)(p0+pm)*F_ + kc + kk], hi, lo);
            Ah[kk][pm] = hi; Al[kk][pm] = lo;
            int kk2 = e >> 7, nn = e & 127;
            Bh[kk2][nn] = g_w2T [(size_t)(kc+kk2)*C_ + nn];
            Bl[kk2][nn] = g_w2Tl[(size_t)(kc+kk2)*C_ + nn];
        }
        __syncthreads();
        FRAG_AND_MMA(Ah, Al, Bh, Bl)
        __syncthreads();
    }
    #pragma unroll
    for (int mt = 0; mt < 4; mt++) {
        int r0 = p0 + warpM*64 + mt*16 + g;
        #pragma unroll
        for (int nt = 0; nt < 4; nt++) {
            int c0 = warpN*32 + nt*8 + 2*tid4;
            float* A4 = acc[mt][nt];
            float2 e0 = *(const float2*)&g_x1[(size_t)r0*C_ + c0];
            float2 e1 = *(const float2*)&g_x1[(size_t)(r0+8)*C_ + c0];
            *(float2*)&g_s2[(size_t)r0*C_ + c0]     = make_float2(A4[0]+e0.x, A4[1]+e0.y);
            *(float2*)&g_s2[(size_t)(r0+8)*C_ + c0] = make_float2(A4[2]+e1.x, A4[3]+e1.y);
        }
    }
}

// ---------------- top-32 per row: exact 4-pass radix select ----------------
__global__ __launch_bounds__(256) void topk_kernel() {
    int row = blockIdx.x;
    const float* Srow = g_S + (size_t)row*N_;
    int t = threadIdx.x;
    unsigned u[8];
    #pragma unroll
    for (int q = 0; q < 8; q++) {
        unsigned b = __float_as_uint(Srow[t + q*256]);
        u[q] = (b & 0x80000000u) ? ~b : (b | 0x80000000u);
    }
    __shared__ unsigned hist[256];
    __shared__ unsigned suffix[256];
    __shared__ unsigned wsum[8];
    __shared__ unsigned sh_prefix;
    __shared__ int sh_need, sh_cnt, sh_eqcnt;
    __shared__ int eqbuf[256];
    if (t == 0) { sh_prefix = 0u; sh_need = K_; }
    int lane = t & 31, wid = t >> 5;

    #pragma unroll
    for (int pass = 0; pass < 4; pass++) {
        int shift = 24 - pass*8;
        hist[t] = 0u;
        __syncthreads();
        unsigned pref = sh_prefix;
        int need = sh_need;
        unsigned mask = (pass == 0) ? 0u : (0xFFFFFFFFu << (shift + 8));
        #pragma unroll
        for (int q = 0; q < 8; q++)
            if ((u[q] & mask) == pref)
                atomicAdd(&hist[(u[q] >> shift) & 255u], 1u);
        __syncthreads();
        int r = 255 - t;
        unsigned val = hist[r];
        #pragma unroll
        for (int o = 1; o < 32; o <<= 1) {
            unsigned up = __shfl_up_sync(0xffffffffu, val, o);
            if (lane >= o) val += up;
        }
        if (lane == 31) wsum[wid] = val;
        __syncthreads();
        #pragma unroll
        for (int w = 0; w < 8; w++) if (w < wid) val += wsum[w];
        suffix[r] = val;
        __syncthreads();
        unsigned nxt = (r == 255) ? 0u : suffix[r + 1];
        if (suffix[r] >= (unsigned)need && nxt < (unsigned)need) {
            sh_prefix = pref | ((unsigned)r << shift);
            sh_need = need - (int)nxt;
        }
        __syncthreads();
    }

    unsigned T = sh_prefix;
    int need_eq = sh_need;
    if (t == 0) { sh_cnt = 0; sh_eqcnt = 0; }
    __syncthreads();
    int* outp = g_idx + row*K_;
    #pragma unroll
    for (int q = 0; q < 8; q++) {
        if (u[q] > T) {
            int pos = atomicAdd(&sh_cnt, 1);
            outp[pos] = t + q*256;
        } else if (u[q] == T) {
            int e = atomicAdd(&sh_eqcnt, 1);
            if (e < 256) eqbuf[e] = t + q*256;
        }
    }
    __syncthreads();
    if (t == 0) {
        int cnt = sh_cnt;
        int m = sh_eqcnt; if (m > 256) m = 256;
        for (int i = 0; i < need_eq; i++) {
            int best = 0x7fffffff, bj = -1;
            for (int j = 0; j < m; j++)
                if (eqbuf[j] < best) { best = eqbuf[j]; bj = j; }
            eqbuf[bj] = 0x7fffffff;
            outp[cnt + i] = best;
        }
    }
}

// ---------------- attention: one block per point, one warp per head ----------
__global__ __launch_bounds__(128) void attn_kernel(const float* __restrict__ x) {
    int p = blockIdx.x;
    int b = p >> 11, n = p & (N_-1);
    int t = threadIdx.x;
    int h = t >> 5, lane = t & 31;
    __shared__ float qs[C_], ks[C_], vs[C_];
    __shared__ float attns[H_][K_];
    __shared__ int idxs[K_];
    const float scale = 0.17677669529663687f;
    qs[t] = g_xq[(size_t)p*C_ + t] * scale;
    ks[t] = g_xk[(size_t)p*C_ + t];
    vs[t] = g_xv[(size_t)p*C_ + t];
    if (t < K_) idxs[t] = g_idx[p*K_ + t];
    __syncthreads();

    int nb = idxs[lane];
    const float* krow = g_xk + ((size_t)(b*N_ + nb))*C_ + h*D_;
    float e = 0.f;
    #pragma unroll
    for (int d = 0; d < D_; d++) e += qs[h*D_ + d] * (krow[d] - ks[h*D_ + d]);
    float mx = e;
    #pragma unroll
    for (int o = 16; o > 0; o >>= 1) mx = fmaxf(mx, __shfl_xor_sync(0xffffffffu, mx, o));
    float ex = __expf(e - mx);
    float sm = ex;
    #pragma unroll
    for (int o = 16; o > 0; o >>= 1) sm += __shfl_xor_sync(0xffffffffu, sm, o);
    attns[h][lane] = ex / sm;
    __syncwarp();

    float vself = vs[h*D_ + lane];
    float acc = 0.f;
    #pragma unroll
    for (int jj = 0; jj < K_; jj++) {
        int nbj = idxs[jj];
        float vnb = g_xv[((size_t)(b*N_ + nbj))*C_ + h*D_ + lane];
        acc += attns[h][jj] * (vnb - vself);
    }
    g_s1[(size_t)p*C_ + t] = x[(size_t)b*C_*N_ + (size_t)t*N_ + n] + acc;
}

// ---------------- BN stats ----------------
__global__ void bnstats_kernel(int which) {
    const float* src = which ? g_s2 : g_s1;
    float* sums      = which ? g_sum2 : g_sum1;
    int t = threadIdx.x;
    const float* base = src + (size_t)blockIdx.x*64*C_;
    float s = 0.f, ss = 0.f;
    #pragma unroll 8
    for (int q = 0; q < 64; q++) { float v = base[(size_t)q*C_ + t]; s += v; ss += v*v; }
    atomicAdd(&sums[t], s);
    atomicAdd(&sums[t + C_], ss);
}

__global__ void bnfin_kernel(int which) {
    const float* sums = which ? g_sum2 : g_sum1;
    float* stat       = which ? g_stat2 : g_stat1;
    int c = threadIdx.x;
    float m = sums[c] * (1.f/(float)P_);
    float var = sums[c + C_] * (1.f/(float)P_) - m*m;
    stat[c] = m;
    stat[c + C_] = rsqrtf(var + EPSbn);
}

__global__ void x1_kernel(const float* __restrict__ g1, const float* __restrict__ b1) {
    int i = blockIdx.x*blockDim.x + threadIdx.x;
    if (i >= P_*C_) return;
    int c = i & (C_-1);
    g_x1[i] = (g_s1[i] - g_stat1[c]) * g_stat1[c + C_] * g1[c] + b1[c];
}

// ---------------- final BN2 + transpose to [B,C,N] ----------------
__global__ void out_kernel(float* __restrict__ out,
                           const float* __restrict__ g2, const float* __restrict__ b2) {
    __shared__ float tile[32][33];
    int b = blockIdx.z;
    int n0 = blockIdx.x*32, c0 = blockIdx.y*32;
    int tx = threadIdx.x, ty = threadIdx.y;
    #pragma unroll
    for (int r = 0; r < 4; r++) {
        int nl = ty + r*8;
        int c = c0 + tx;
        float v = g_s2[(size_t)(b*N_ + n0 + nl)*C_ + c];
        v = (v - g_stat2[c]) * g_stat2[c + C_] * g2[c] + b2[c];
        tile[nl][tx] = v;
    }
    __syncthreads();
    #pragma unroll
    for (int r = 0; r < 4; r++) {
        int cl = ty + r*8;
        out[(size_t)b*C_*N_ + (size_t)(c0 + cl)*N_ + n0 + tx] = tile[tx][cl];
    }
}

// ---------------- launch ----------------
extern "C" void kernel_launch(void* const* d_in, const int* in_sizes, int n_in,
                              void* d_out, int out_size) {
    const float* x  = (const float*)d_in[0];
    const float* wq = (const float*)d_in[1];
    const float* wk = (const float*)d_in[2];
    const float* wv = (const float*)d_in[3];
    const float* w1 = (const float*)d_in[4];
    const float* w2 = (const float*)d_in[5];
    const float* g1 = (const float*)d_in[6];
    const float* b1 = (const float*)d_in[7];
    const float* g2 = (const float*)d_in[8];
    const float* b2 = (const float*)d_in[9];
    float* out = (float*)d_out;

    void *pwq, *pwk, *pwv, *pw1, *pw2;
    void *pwql, *pwkl, *pwvl, *pw1l, *pw2l;
    cudaGetSymbolAddress(&pwq, g_wqT);   cudaGetSymbolAddress(&pwql, g_wqTl);
    cudaGetSymbolAddress(&pwk, g_wkT);   cudaGetSymbolAddress(&pwkl, g_wkTl);
    cudaGetSymbolAddress(&pwv, g_wvT);   cudaGetSymbolAddress(&pwvl, g_wvTl);
    cudaGetSymbolAddress(&pw1, g_w1T);   cudaGetSymbolAddress(&pw1l, g_w1Tl);
    cudaGetSymbolAddress(&pw2, g_w2T);   cudaGetSymbolAddress(&pw2l, g_w2Tl);

    init_kernel<<<1, 256>>>();
    colnorm_kernel<<<P_/256, 256>>>(x);
    tp_kernel<<<(C_*C_)/256, 256>>>(wq, (unsigned*)pwq, (unsigned*)pwql, C_, C_);
    tp_kernel<<<(C_*C_)/256, 256>>>(wk, (unsigned*)pwk, (unsigned*)pwkl, C_, C_);
    tp_kernel<<<(C_*C_)/256, 256>>>(wv, (unsigned*)pwv, (unsigned*)pwvl, C_, C_);
    tp_kernel<<<(F_*C_)/256, 256>>>(w1, (unsigned*)pw1, (unsigned*)pw1l, F_, C_);
    tp_kernel<<<(C_*F_)/256, 256>>>(w2, (unsigned*)pw2, (unsigned*)pw2l, C_, F_);

    score_tc<<<dim3(136, 1, B_), 256>>>(x);
    topk_kernel<<<P_, 256>>>();
    proj_tc<<<dim3(16, 3, B_), 256>>>(x);
    attn_kernel<<<P_, 128>>>(x);

    bnstats_kernel<<<P_/64, 128>>>(0);
    bnfin_kernel<<<1, 128>>>(0);
    x1_kernel<<<(P_*C_)/256, 256>>>(g1, b1);

    ffn1_tc<<<dim3(F_/128, P_/128), 256>>>();
    ffn2_tc<<<dim3(1, P_/128), 256>>>();

    bnstats_kernel<<<P_/64, 128>>>(1);
    bnfin_kernel<<<1, 128>>>(1);

    out_kernel<<<dim3(N_/32, C_/32, B_), dim3(32, 8)>>>(out, g2, b2);
}

// round 5
// speedup vs baseline: 1.3805x; 1.3805x over previous
#include <cuda_runtime.h>
#include <math.h>

#define B_ 8
#define C_ 128
#define N_ 2048
#define H_ 4
#define K_ 32
#define D_ 32
#define F_ 512
#define P_ (B_*N_)
#define EPSbn 1e-5f

// ---------------- scratch (static device allocations only) ----------------
__device__ float g_S[B_*N_*N_];        // 128MB scores; later reused as hT [o][p] for FFN
__device__ int   g_idx[P_*K_];
__device__ float g_xq[P_*C_];
__device__ float g_xk[P_*C_];
__device__ float g_xv[P_*C_];
__device__ float g_x2[P_];
__device__ float g_s1[P_*C_];
__device__ float g_x1[P_*C_];          // [p][c]
__device__ float g_x1T[C_*P_];         // [c][p]
__device__ float g_s2[P_*C_];
__device__ float g_sum1[2*C_];
__device__ float g_sum2[2*C_];
__device__ float g_stat1[2*C_];
__device__ float g_stat2[2*C_];
__device__ float g_wqkvT[C_*384];      // [cin][3*cout]
__device__ float g_w1T[C_*F_];         // [cin][o]
__device__ float g_w2T[F_*C_];         // [o][cout]

// ---------------- init ----------------
__global__ void init_kernel() {
    int t = threadIdx.x;
    if (t < 2*C_) { g_sum1[t] = 0.f; g_sum2[t] = 0.f; }
}

// ---------------- transpose weights: dst[c*ldd + off + r] = src[r*Cc + c] ----
__global__ void tpf_kernel(const float* __restrict__ src, float* __restrict__ dst,
                           int R, int Cc, int ldd, int off) {
    int i = blockIdx.x*256 + threadIdx.x;
    if (i >= R*Cc) return;
    int r = i / Cc, c = i % Cc;
    dst[(size_t)c*ldd + off + r] = src[i];
}

// ---------------- per-point squared norms ----------------
__global__ void colnorm_kernel(const float* __restrict__ x) {
    int p = blockIdx.x*blockDim.x + threadIdx.x;
    if (p >= P_) return;
    int b = p / N_, n = p % N_;
    const float* xb = x + (size_t)b*C_*N_ + n;
    float s = 0.f;
    #pragma unroll
    for (int c = 0; c < C_; c++) { float v = xb[(size_t)c*N_]; s += v*v; }
    g_x2[p] = s;
}

// ---------------- shared SGEMM mainloop: 128x128 tile, 8x8 micro, BK=8 -------
// A, B in k-major layout: elem(k, i) = ptr[k*stride + i], ptr pre-offset to tile.
__device__ __forceinline__ void sgemm_body(
    const float* __restrict__ Ag, long sA,
    const float* __restrict__ Bg, long sB,
    int KD, float acc[8][8], float (*As)[128], float (*Bs)[128], int t)
{
    int tx = t & 15, ty = t >> 4;
    int kk = t >> 5, mm = (t*4) & 127;
    for (int kc = 0; kc < KD; kc += 8) {
        *(float4*)&As[kk][mm] = *(const float4*)&Ag[(long)(kc+kk)*sA + mm];
        *(float4*)&Bs[kk][mm] = *(const float4*)&Bg[(long)(kc+kk)*sB + mm];
        __syncthreads();
        #pragma unroll
        for (int k = 0; k < 8; k++) {
            float a[8], b[8];
            *(float4*)(a)   = *(float4*)&As[k][ty*8];
            *(float4*)(a+4) = *(float4*)&As[k][ty*8+4];
            *(float4*)(b)   = *(float4*)&Bs[k][tx*8];
            *(float4*)(b+4) = *(float4*)&Bs[k][tx*8+4];
            #pragma unroll
            for (int iy = 0; iy < 8; iy++)
                #pragma unroll
                for (int ix = 0; ix < 8; ix++) acc[iy][ix] += a[iy]*b[ix];
        }
        __syncthreads();
    }
}

#define ACC_INIT float acc[8][8];                                   \
    _Pragma("unroll") for (int iy = 0; iy < 8; iy++)                \
    _Pragma("unroll") for (int ix = 0; ix < 8; ix++) acc[iy][ix] = 0.f;

// ---------------- score: S[n,m] = dot(x_n,x_m) - 0.5||x_m||^2, symmetric -----
__global__ __launch_bounds__(256) void score_sgemm(const float* __restrict__ x) {
    const int T = 16;                      // 16 tiles of 128; pairs = 136
    int L = blockIdx.x;
    int i = 0, rem = L;
    while (rem >= T - i) { rem -= (T - i); i++; }
    int j = i + rem;
    int n0 = i*128, m0 = j*128;
    int b = blockIdx.z;
    const float* xb  = x + (size_t)b*C_*N_;
    float* Sb        = g_S + (size_t)b*N_*N_;
    const float* x2b = g_x2 + b*N_;

    __shared__ float As[8][128], Bs[8][128];
    int t = threadIdx.x, tx = t & 15, ty = t >> 4;
    ACC_INIT
    sgemm_body(xb + n0, N_, xb + m0, N_, C_, acc, As, Bs, t);

    int r0 = n0 + ty*8, c0 = m0 + tx*8;
    float x2r[8], x2c[8];
    #pragma unroll
    for (int q = 0; q < 8; q++) { x2r[q] = x2b[r0+q]; x2c[q] = 0.5f*x2b[c0+q]; }
    #pragma unroll
    for (int iy = 0; iy < 8; iy++) {
        float* row = &Sb[(size_t)(r0+iy)*N_ + c0];
        float4 v0 = make_float4(acc[iy][0]-x2c[0], acc[iy][1]-x2c[1],
                                acc[iy][2]-x2c[2], acc[iy][3]-x2c[3]);
        float4 v1 = make_float4(acc[iy][4]-x2c[4], acc[iy][5]-x2c[5],
                                acc[iy][6]-x2c[6], acc[iy][7]-x2c[7]);
        *(float4*)(row)   = v0;
        *(float4*)(row+4) = v1;
    }
    if (i != j) {
        #pragma unroll
        for (int ix = 0; ix < 8; ix++) {
            float* col = &Sb[(size_t)(c0+ix)*N_ + r0];
            float4 w0 = make_float4(acc[0][ix]-0.5f*x2r[0], acc[1][ix]-0.5f*x2r[1],
                                    acc[2][ix]-0.5f*x2r[2], acc[3][ix]-0.5f*x2r[3]);
            float4 w1 = make_float4(acc[4][ix]-0.5f*x2r[4], acc[5][ix]-0.5f*x2r[5],
                                    acc[6][ix]-0.5f*x2r[6], acc[7][ix]-0.5f*x2r[7]);
            *(float4*)(col)   = w0;
            *(float4*)(col+4) = w1;
        }
    }
}

// ---------------- fused q/k/v projection: out[p][o] = sum_c x[b,c,n] w[o,c] ---
__global__ __launch_bounds__(256) void proj_sgemm(const float* __restrict__ x) {
    int widx = blockIdx.x;                 // 0,1,2 -> q,k,v (128 cols each)
    int n0 = blockIdx.y*128;
    int b = blockIdx.z;
    const float* xb = x + (size_t)b*C_*N_;
    float* outp = (widx == 0 ? g_xq : widx == 1 ? g_xk : g_xv) + (size_t)b*N_*C_;

    __shared__ float As[8][128], Bs[8][128];
    int t = threadIdx.x, tx = t & 15, ty = t >> 4;
    ACC_INIT
    sgemm_body(xb + n0, N_, g_wqkvT + widx*128, 384, C_, acc, As, Bs, t);

    #pragma unroll
    for (int iy = 0; iy < 8; iy++) {
        int r = n0 + ty*8 + iy;
        float* row = &outp[(size_t)r*C_ + tx*8];
        *(float4*)(row)   = make_float4(acc[iy][0], acc[iy][1], acc[iy][2], acc[iy][3]);
        *(float4*)(row+4) = make_float4(acc[iy][4], acc[iy][5], acc[iy][6], acc[iy][7]);
    }
}

// ---------------- ffn1: hT[o][p] = leaky(sum_c x1T[c][p] * w1T[c][o]) ---------
__global__ __launch_bounds__(256) void ffn1_sgemm() {
    int o0 = blockIdx.x*128;
    int p0 = blockIdx.y*128;
    float* hT = g_S;                       // reuse scores buffer: [o][p]

    __shared__ float As[8][128], Bs[8][128];
    int t = threadIdx.x, tx = t & 15, ty = t >> 4;
    ACC_INIT
    sgemm_body(g_x1T + p0, P_, g_w1T + o0, F_, C_, acc, As, Bs, t);

    #pragma unroll
    for (int ix = 0; ix < 8; ix++) {
        int col = o0 + tx*8 + ix;
        float v[8];
        #pragma unroll
        for (int iy = 0; iy < 8; iy++) {
            float u = acc[iy][ix];
            v[iy] = u > 0.f ? u : 0.2f*u;
        }
        float* cp = &hT[(size_t)col*P_ + p0 + ty*8];
        *(float4*)(cp)   = make_float4(v[0], v[1], v[2], v[3]);
        *(float4*)(cp+4) = make_float4(v[4], v[5], v[6], v[7]);
    }
}

// ---------------- ffn2: s2[p][c] = x1[p][c] + sum_o hT[o][p] * w2T[o][c] ------
__global__ __launch_bounds__(256) void ffn2_sgemm() {
    int p0 = blockIdx.y*128;
    const float* hT = g_S;

    __shared__ float As[8][128], Bs[8][128];
    int t = threadIdx.x, tx = t & 15, ty = t >> 4;
    ACC_INIT
    sgemm_body(hT + p0, P_, g_w2T, C_, F_, acc, As, Bs, t);

    #pragma unroll
    for (int iy = 0; iy < 8; iy++) {
        int r = p0 + ty*8 + iy;
        const float* resp = &g_x1[(size_t)r*C_ + tx*8];
        float* op = &g_s2[(size_t)r*C_ + tx*8];
        float4 e0 = *(const float4*)(resp);
        float4 e1 = *(const float4*)(resp+4);
        *(float4*)(op)   = make_float4(acc[iy][0]+e0.x, acc[iy][1]+e0.y,
                                       acc[iy][2]+e0.z, acc[iy][3]+e0.w);
        *(float4*)(op+4) = make_float4(acc[iy][4]+e1.x, acc[iy][5]+e1.y,
                                       acc[iy][6]+e1.z, acc[iy][7]+e1.w);
    }
}

// ---------------- top-32 per row: exact 4-pass radix select ----------------
__global__ __launch_bounds__(256) void topk_kernel() {
    int row = blockIdx.x;
    const float* Srow = g_S + (size_t)row*N_;
    int t = threadIdx.x;
    unsigned u[8];
    #pragma unroll
    for (int q = 0; q < 8; q++) {
        unsigned b = __float_as_uint(Srow[t + q*256]);
        u[q] = (b & 0x80000000u) ? ~b : (b | 0x80000000u);
    }
    __shared__ unsigned hist[256];
    __shared__ unsigned suffix[256];
    __shared__ unsigned wsum[8];
    __shared__ unsigned sh_prefix;
    __shared__ int sh_need, sh_cnt, sh_eqcnt;
    __shared__ int eqbuf[256];
    if (t == 0) { sh_prefix = 0u; sh_need = K_; }
    int lane = t & 31, wid = t >> 5;

    #pragma unroll
    for (int pass = 0; pass < 4; pass++) {
        int shift = 24 - pass*8;
        hist[t] = 0u;
        __syncthreads();
        unsigned pref = sh_prefix;
        int need = sh_need;
        unsigned mask = (pass == 0) ? 0u : (0xFFFFFFFFu << (shift + 8));
        #pragma unroll
        for (int q = 0; q < 8; q++)
            if ((u[q] & mask) == pref)
                atomicAdd(&hist[(u[q] >> shift) & 255u], 1u);
        __syncthreads();
        int r = 255 - t;
        unsigned val = hist[r];
        #pragma unroll
        for (int o = 1; o < 32; o <<= 1) {
            unsigned up = __shfl_up_sync(0xffffffffu, val, o);
            if (lane >= o) val += up;
        }
        if (lane == 31) wsum[wid] = val;
        __syncthreads();
        #pragma unroll
        for (int w = 0; w < 8; w++) if (w < wid) val += wsum[w];
        suffix[r] = val;
        __syncthreads();
        unsigned nxt = (r == 255) ? 0u : suffix[r + 1];
        if (suffix[r] >= (unsigned)need && nxt < (unsigned)need) {
            sh_prefix = pref | ((unsigned)r << shift);
            sh_need = need - (int)nxt;
        }
        __syncthreads();
    }

    unsigned T = sh_prefix;
    int need_eq = sh_need;
    if (t == 0) { sh_cnt = 0; sh_eqcnt = 0; }
    __syncthreads();
    int* outp = g_idx + row*K_;
    #pragma unroll
    for (int q = 0; q < 8; q++) {
        if (u[q] > T) {
            int pos = atomicAdd(&sh_cnt, 1);
            outp[pos] = t + q*256;
        } else if (u[q] == T) {
            int e = atomicAdd(&sh_eqcnt, 1);
            if (e < 256) eqbuf[e] = t + q*256;
        }
    }
    __syncthreads();
    if (t == 0) {
        int cnt = sh_cnt;
        int m = sh_eqcnt; if (m > 256) m = 256;
        for (int i = 0; i < need_eq; i++) {
            int best = 0x7fffffff, bj = -1;
            for (int j = 0; j < m; j++)
                if (eqbuf[j] < best) { best = eqbuf[j]; bj = j; }
            eqbuf[bj] = 0x7fffffff;
            outp[cnt + i] = best;
        }
    }
}

// ---------------- attention: one block per point, one warp per head ----------
__global__ __launch_bounds__(128) void attn_kernel(const float* __restrict__ x) {
    int p = blockIdx.x;
    int b = p >> 11, n = p & (N_-1);
    int t = threadIdx.x;
    int h = t >> 5, lane = t & 31;
    __shared__ float qs[C_], ks[C_], vs[C_];
    __shared__ float attns[H_][K_];
    __shared__ int idxs[K_];
    const float scale = 0.17677669529663687f;
    qs[t] = g_xq[(size_t)p*C_ + t] * scale;
    ks[t] = g_xk[(size_t)p*C_ + t];
    vs[t] = g_xv[(size_t)p*C_ + t];
    if (t < K_) idxs[t] = g_idx[p*K_ + t];
    __syncthreads();

    int nb = idxs[lane];
    const float* krow = g_xk + ((size_t)(b*N_ + nb))*C_ + h*D_;
    float e = 0.f;
    #pragma unroll
    for (int d = 0; d < D_; d++) e += qs[h*D_ + d] * (krow[d] - ks[h*D_ + d]);
    float mx = e;
    #pragma unroll
    for (int o = 16; o > 0; o >>= 1) mx = fmaxf(mx, __shfl_xor_sync(0xffffffffu, mx, o));
    float ex = __expf(e - mx);
    float sm = ex;
    #pragma unroll
    for (int o = 16; o > 0; o >>= 1) sm += __shfl_xor_sync(0xffffffffu, sm, o);
    attns[h][lane] = ex / sm;
    __syncwarp();

    float vself = vs[h*D_ + lane];
    float acc = 0.f;
    #pragma unroll
    for (int jj = 0; jj < K_; jj++) {
        int nbj = idxs[jj];
        float vnb = g_xv[((size_t)(b*N_ + nbj))*C_ + h*D_ + lane];
        acc += attns[h][jj] * (vnb - vself);
    }
    g_s1[(size_t)p*C_ + t] = x[(size_t)b*C_*N_ + (size_t)t*N_ + n] + acc;
}

// ---------------- BN stats ----------------
__global__ void bnstats_kernel(int which) {
    const float* src = which ? g_s2 : g_s1;
    float* sums      = which ? g_sum2 : g_sum1;
    int t = threadIdx.x;
    const float* base = src + (size_t)blockIdx.x*64*C_;
    float s = 0.f, ss = 0.f;
    #pragma unroll 8
    for (int q = 0; q < 64; q++) { float v = base[(size_t)q*C_ + t]; s += v; ss += v*v; }
    atomicAdd(&sums[t], s);
    atomicAdd(&sums[t + C_], ss);
}

__global__ void bnfin_kernel(int which) {
    const float* sums = which ? g_sum2 : g_sum1;
    float* stat       = which ? g_stat2 : g_stat1;
    int c = threadIdx.x;
    float m = sums[c] * (1.f/(float)P_);
    float var = sums[c + C_] * (1.f/(float)P_) - m*m;
    stat[c] = m;
    stat[c + C_] = rsqrtf(var + EPSbn);
}

__global__ void x1_kernel(const float* __restrict__ g1, const float* __restrict__ b1) {
    int i = blockIdx.x*blockDim.x + threadIdx.x;
    if (i >= P_*C_) return;
    int c = i & (C_-1);
    int p = i >> 7;
    float v = (g_s1[i] - g_stat1[c]) * g_stat1[c + C_] * g1[c] + b1[c];
    g_x1[i] = v;
    g_x1T[(size_t)c*P_ + p] = v;
}

// ---------------- final BN2 + transpose to [B,C,N] ----------------
__global__ void out_kernel(float* __restrict__ out,
                           const float* __restrict__ g2, const float* __restrict__ b2) {
    __shared__ float tile[32][33];
    int b = blockIdx.z;
    int n0 = blockIdx.x*32, c0 = blockIdx.y*32;
    int tx = threadIdx.x, ty = threadIdx.y;
    #pragma unroll
    for (int r = 0; r < 4; r++) {
        int nl = ty + r*8;
        int c = c0 + tx;
        float v = g_s2[(size_t)(b*N_ + n0 + nl)*C_ + c];
        v = (v - g_stat2[c]) * g_stat2[c + C_] * g2[c] + b2[c];
        tile[nl][tx] = v;
    }
    __syncthreads();
    #pragma unroll
    for (int r = 0; r < 4; r++) {
        int cl = ty + r*8;
        out[(size_t)b*C_*N_ + (size_t)(c0 + cl)*N_ + n0 + tx] = tile[tx][cl];
    }
}

// ---------------- launch ----------------
extern "C" void kernel_launch(void* const* d_in, const int* in_sizes, int n_in,
                              void* d_out, int out_size) {
    const float* x  = (const float*)d_in[0];
    const float* wq = (const float*)d_in[1];
    const float* wk = (const float*)d_in[2];
    const float* wv = (const float*)d_in[3];
    const float* w1 = (const float*)d_in[4];
    const float* w2 = (const float*)d_in[5];
    const float* g1 = (const float*)d_in[6];
    const float* b1 = (const float*)d_in[7];
    const float* g2 = (const float*)d_in[8];
    const float* b2 = (const float*)d_in[9];
    float* out = (float*)d_out;

    void *pwqkv, *pw1, *pw2;
    cudaGetSymbolAddress(&pwqkv, g_wqkvT);
    cudaGetSymbolAddress(&pw1, g_w1T);
    cudaGetSymbolAddress(&pw2, g_w2T);

    init_kernel<<<1, 256>>>();
    colnorm_kernel<<<P_/256, 256>>>(x);
    tpf_kernel<<<(C_*C_)/256, 256>>>(wq, (float*)pwqkv, C_, C_, 384, 0);
    tpf_kernel<<<(C_*C_)/256, 256>>>(wk, (float*)pwqkv, C_, C_, 384, 128);
    tpf_kernel<<<(C_*C_)/256, 256>>>(wv, (float*)pwqkv, C_, C_, 384, 256);
    tpf_kernel<<<(F_*C_)/256, 256>>>(w1, (float*)pw1, F_, C_, F_, 0);
    tpf_kernel<<<(C_*F_)/256, 256>>>(w2, (float*)pw2, C_, F_, C_, 0);

    score_sgemm<<<dim3(136, 1, B_), 256>>>(x);
    topk_kernel<<<P_, 256>>>();
    proj_sgemm<<<dim3(3, N_/128, B_), 256>>>(x);
    attn_kernel<<<P_, 128>>>(x);

    bnstats_kernel<<<P_/64, 128>>>(0);
    bnfin_kernel<<<1, 128>>>(0);
    x1_kernel<<<(P_*C_)/256, 256>>>(g1, b1);

    ffn1_sgemm<<<dim3(F_/128, P_/128), 256>>>();
    ffn2_sgemm<<<dim3(1, P_/128), 256>>>();

    bnstats_kernel<<<P_/64, 128>>>(1);
    bnfin_kernel<<<1, 128>>>(1);

    out_kernel<<<dim3(N_/32, C_/32, B_), dim3(32, 8)>>>(out, g2, b2);
}

// round 6
// speedup vs baseline: 1.6419x; 1.1893x over previous
#include <cuda_runtime.h>
#include <math.h>

#define B_ 8
#define C_ 128
#define N_ 2048
#define H_ 4
#define K_ 32
#define D_ 32
#define F_ 512
#define P_ (B_*N_)
#define EPSbn 1e-5f

// ---------------- scratch (static device allocations only) ----------------
__device__ float g_S[B_*N_*N_];        // 128MB scores; later reused as hT [o][p] for FFN
__device__ int   g_idx[P_*K_];
__device__ float g_xq[P_*C_];
__device__ float g_xk[P_*C_];
__device__ float g_xv[P_*C_];
__device__ float g_x2[P_];
__device__ float g_s1[P_*C_];
__device__ float g_x1[P_*C_];          // [p][c]
__device__ float g_x1T[C_*P_];         // [c][p]
__device__ float g_s2[P_*C_];
__device__ float g_sum1[2*C_];
__device__ float g_sum2[2*C_];
__device__ float g_stat1[2*C_];
__device__ float g_stat2[2*C_];
__device__ float g_wqkvT[C_*384];      // [cin][3*cout]
__device__ float g_w1T[C_*F_];         // [cin][o]
__device__ float g_w2T[F_*C_];         // [o][cout]

// ---------------- init ----------------
__global__ void init_kernel() {
    int t = threadIdx.x;
    if (t < 2*C_) { g_sum1[t] = 0.f; g_sum2[t] = 0.f; }
}

// ---------------- transpose weights: dst[c*ldd + off + r] = src[r*Cc + c] ----
__global__ void tpf_kernel(const float* __restrict__ src, float* __restrict__ dst,
                           int R, int Cc, int ldd, int off) {
    int i = blockIdx.x*256 + threadIdx.x;
    if (i >= R*Cc) return;
    int r = i / Cc, c = i % Cc;
    dst[(size_t)c*ldd + off + r] = src[i];
}

// ---------------- per-point squared norms ----------------
__global__ void colnorm_kernel(const float* __restrict__ x) {
    int p = blockIdx.x*blockDim.x + threadIdx.x;
    if (p >= P_) return;
    int b = p / N_, n = p % N_;
    const float* xb = x + (size_t)b*C_*N_ + n;
    float s = 0.f;
    #pragma unroll
    for (int c = 0; c < C_; c++) { float v = xb[(size_t)c*N_]; s += v*v; }
    g_x2[p] = s;
}

// ---------------- shared SGEMM mainloop: 128x128 tile, 8x8 micro, BK=8 -------
__device__ __forceinline__ void sgemm_body(
    const float* __restrict__ Ag, long sA,
    const float* __restrict__ Bg, long sB,
    int KD, float acc[8][8], float (*As)[128], float (*Bs)[128], int t)
{
    int tx = t & 15, ty = t >> 4;
    int kk = t >> 5, mm = (t*4) & 127;
    for (int kc = 0; kc < KD; kc += 8) {
        *(float4*)&As[kk][mm] = *(const float4*)&Ag[(long)(kc+kk)*sA + mm];
        *(float4*)&Bs[kk][mm] = *(const float4*)&Bg[(long)(kc+kk)*sB + mm];
        __syncthreads();
        #pragma unroll
        for (int k = 0; k < 8; k++) {
            float a[8], b[8];
            *(float4*)(a)   = *(float4*)&As[k][ty*8];
            *(float4*)(a+4) = *(float4*)&As[k][ty*8+4];
            *(float4*)(b)   = *(float4*)&Bs[k][tx*8];
            *(float4*)(b+4) = *(float4*)&Bs[k][tx*8+4];
            #pragma unroll
            for (int iy = 0; iy < 8; iy++)
                #pragma unroll
                for (int ix = 0; ix < 8; ix++) acc[iy][ix] += a[iy]*b[ix];
        }
        __syncthreads();
    }
}

#define ACC_INIT float acc[8][8];                                   \
    _Pragma("unroll") for (int iy = 0; iy < 8; iy++)                \
    _Pragma("unroll") for (int ix = 0; ix < 8; ix++) acc[iy][ix] = 0.f;

// ---------------- score: S[n,m] = dot(x_n,x_m) - 0.5||x_m||^2, symmetric -----
// Mirror tile is written via smem transpose so ALL global stores are coalesced.
__global__ __launch_bounds__(256) void score_sgemm(const float* __restrict__ x) {
    const int T = 16;
    int L = blockIdx.x;
    int i = 0, rem = L;
    while (rem >= T - i) { rem -= (T - i); i++; }
    int j = i + rem;
    int n0 = i*128, m0 = j*128;
    int b = blockIdx.z;
    const float* xb  = x + (size_t)b*C_*N_;
    float* Sb        = g_S + (size_t)b*N_*N_;
    const float* x2b = g_x2 + b*N_;

    __shared__ float As[8][128], Bs[8][128];
    __shared__ float sbuf[16][132];
    int t = threadIdx.x, tx = t & 15, ty = t >> 4;
    ACC_INIT
    sgemm_body(xb + n0, N_, xb + m0, N_, C_, acc, As, Bs, t);

    int r0 = n0 + ty*8, c0 = m0 + tx*8;
    float x2r[8], x2c[8];
    #pragma unroll
    for (int q = 0; q < 8; q++) { x2r[q] = x2b[r0+q]; x2c[q] = 0.5f*x2b[c0+q]; }
    #pragma unroll
    for (int iy = 0; iy < 8; iy++) {
        float* row = &Sb[(size_t)(r0+iy)*N_ + c0];
        *(float4*)(row)   = make_float4(acc[iy][0]-x2c[0], acc[iy][1]-x2c[1],
                                        acc[iy][2]-x2c[2], acc[iy][3]-x2c[3]);
        *(float4*)(row+4) = make_float4(acc[iy][4]-x2c[4], acc[iy][5]-x2c[5],
                                        acc[iy][6]-x2c[6], acc[iy][7]-x2c[7]);
    }
    if (i != j) {
        int lr = t >> 4, lc = (t & 15)*8;      // writer mapping for output phase
        #pragma unroll
        for (int ix = 0; ix < 8; ix++) {
            __syncthreads();
            // stage mirror rows (c0+tx*8+ix) x cols (n0 + ty*8+iy) into sbuf[tx][ty*8+iy]
            #pragma unroll
            for (int iy = 0; iy < 8; iy++)
                sbuf[tx][ty*8 + iy] = acc[iy][ix] - 0.5f*x2r[iy];
            __syncthreads();
            // coalesced write: 16 threads cover one mirror row of 128 cols
            float* dst = &Sb[(size_t)(m0 + lr*8 + ix)*N_ + n0 + lc];
            *(float4*)(dst)   = make_float4(sbuf[lr][lc],   sbuf[lr][lc+1],
                                            sbuf[lr][lc+2], sbuf[lr][lc+3]);
            *(float4*)(dst+4) = make_float4(sbuf[lr][lc+4], sbuf[lr][lc+5],
                                            sbuf[lr][lc+6], sbuf[lr][lc+7]);
        }
    }
}

// ---------------- fused q/k/v projection ----------------
__global__ __launch_bounds__(256) void proj_sgemm(const float* __restrict__ x) {
    int widx = blockIdx.x;
    int n0 = blockIdx.y*128;
    int b = blockIdx.z;
    const float* xb = x + (size_t)b*C_*N_;
    float* outp = (widx == 0 ? g_xq : widx == 1 ? g_xk : g_xv) + (size_t)b*N_*C_;

    __shared__ float As[8][128], Bs[8][128];
    int t = threadIdx.x, tx = t & 15, ty = t >> 4;
    ACC_INIT
    sgemm_body(xb + n0, N_, g_wqkvT + widx*128, 384, C_, acc, As, Bs, t);

    #pragma unroll
    for (int iy = 0; iy < 8; iy++) {
        int r = n0 + ty*8 + iy;
        float* row = &outp[(size_t)r*C_ + tx*8];
        *(float4*)(row)   = make_float4(acc[iy][0], acc[iy][1], acc[iy][2], acc[iy][3]);
        *(float4*)(row+4) = make_float4(acc[iy][4], acc[iy][5], acc[iy][6], acc[iy][7]);
    }
}

// ---------------- ffn1: hT[o][p] = leaky(sum_c x1T[c][p] * w1T[c][o]) ---------
__global__ __launch_bounds__(256) void ffn1_sgemm() {
    int o0 = blockIdx.x*128;
    int p0 = blockIdx.y*128;
    float* hT = g_S;

    __shared__ float As[8][128], Bs[8][128];
    int t = threadIdx.x, tx = t & 15, ty = t >> 4;
    ACC_INIT
    sgemm_body(g_x1T + p0, P_, g_w1T + o0, F_, C_, acc, As, Bs, t);

    #pragma unroll
    for (int ix = 0; ix < 8; ix++) {
        int col = o0 + tx*8 + ix;
        float v[8];
        #pragma unroll
        for (int iy = 0; iy < 8; iy++) {
            float u = acc[iy][ix];
            v[iy] = u > 0.f ? u : 0.2f*u;
        }
        float* cp = &hT[(size_t)col*P_ + p0 + ty*8];
        *(float4*)(cp)   = make_float4(v[0], v[1], v[2], v[3]);
        *(float4*)(cp+4) = make_float4(v[4], v[5], v[6], v[7]);
    }
}

// ---------------- ffn2: s2[p][c] = x1[p][c] + sum_o hT[o][p] * w2T[o][c] ------
__global__ __launch_bounds__(256) void ffn2_sgemm() {
    int p0 = blockIdx.y*128;
    const float* hT = g_S;

    __shared__ float As[8][128], Bs[8][128];
    int t = threadIdx.x, tx = t & 15, ty = t >> 4;
    ACC_INIT
    sgemm_body(hT + p0, P_, g_w2T, C_, F_, acc, As, Bs, t);

    #pragma unroll
    for (int iy = 0; iy < 8; iy++) {
        int r = p0 + ty*8 + iy;
        const float* resp = &g_x1[(size_t)r*C_ + tx*8];
        float* op = &g_s2[(size_t)r*C_ + tx*8];
        float4 e0 = *(const float4*)(resp);
        float4 e1 = *(const float4*)(resp+4);
        *(float4*)(op)   = make_float4(acc[iy][0]+e0.x, acc[iy][1]+e0.y,
                                       acc[iy][2]+e0.z, acc[iy][3]+e0.w);
        *(float4*)(op+4) = make_float4(acc[iy][4]+e1.x, acc[iy][5]+e1.y,
                                       acc[iy][6]+e1.z, acc[iy][7]+e1.w);
    }
}

// ---------------- top-32 per row: exact 4-pass radix select ----------------
__global__ __launch_bounds__(256) void topk_kernel() {
    int row = blockIdx.x;
    const float* Srow = g_S + (size_t)row*N_;
    int t = threadIdx.x;
    unsigned u[8];
    #pragma unroll
    for (int q = 0; q < 8; q++) {
        unsigned b = __float_as_uint(Srow[t + q*256]);
        u[q] = (b & 0x80000000u) ? ~b : (b | 0x80000000u);
    }
    __shared__ unsigned hist[256];
    __shared__ unsigned suffix[256];
    __shared__ unsigned wsum[8];
    __shared__ unsigned sh_prefix;
    __shared__ int sh_need, sh_cnt, sh_eqcnt;
    __shared__ int eqbuf[256];
    if (t == 0) { sh_prefix = 0u; sh_need = K_; }
    int lane = t & 31, wid = t >> 5;

    #pragma unroll
    for (int pass = 0; pass < 4; pass++) {
        int shift = 24 - pass*8;
        hist[t] = 0u;
        __syncthreads();
        unsigned pref = sh_prefix;
        int need = sh_need;
        unsigned mask = (pass == 0) ? 0u : (0xFFFFFFFFu << (shift + 8));
        #pragma unroll
        for (int q = 0; q < 8; q++)
            if ((u[q] & mask) == pref)
                atomicAdd(&hist[(u[q] >> shift) & 255u], 1u);
        __syncthreads();
        int r = 255 - t;
        unsigned val = hist[r];
        #pragma unroll
        for (int o = 1; o < 32; o <<= 1) {
            unsigned up = __shfl_up_sync(0xffffffffu, val, o);
            if (lane >= o) val += up;
        }
        if (lane == 31) wsum[wid] = val;
        __syncthreads();
        #pragma unroll
        for (int w = 0; w < 8; w++) if (w < wid) val += wsum[w];
        suffix[r] = val;
        __syncthreads();
        unsigned nxt = (r == 255) ? 0u : suffix[r + 1];
        if (suffix[r] >= (unsigned)need && nxt < (unsigned)need) {
            sh_prefix = pref | ((unsigned)r << shift);
            sh_need = need - (int)nxt;
        }
        __syncthreads();
    }

    unsigned T = sh_prefix;
    int need_eq = sh_need;
    if (t == 0) { sh_cnt = 0; sh_eqcnt = 0; }
    __syncthreads();
    int* outp = g_idx + row*K_;
    #pragma unroll
    for (int q = 0; q < 8; q++) {
        if (u[q] > T) {
            int pos = atomicAdd(&sh_cnt, 1);
            outp[pos] = t + q*256;
        } else if (u[q] == T) {
            int e = atomicAdd(&sh_eqcnt, 1);
            if (e < 256) eqbuf[e] = t + q*256;
        }
    }
    __syncthreads();
    if (t == 0) {
        int cnt = sh_cnt;
        int m = sh_eqcnt; if (m > 256) m = 256;
        for (int i = 0; i < need_eq; i++) {
            int best = 0x7fffffff, bj = -1;
            for (int j = 0; j < m; j++)
                if (eqbuf[j] < best) { best = eqbuf[j]; bj = j; }
            eqbuf[bj] = 0x7fffffff;
            outp[cnt + i] = best;
        }
    }
}

// ---------------- attention: smem-staged neighbor K/V (coalesced gather) ------
__global__ __launch_bounds__(128) void attn_kernel(const float* __restrict__ x) {
    int p = blockIdx.x;
    int b = p >> 11, n = p & (N_-1);
    int t = threadIdx.x;
    int h = t >> 5, lane = t & 31;
    __shared__ float qs[C_], ks[C_], vs[C_];
    __shared__ float kn[K_][C_+1], vn[K_][C_+1];   // pad 129: conflict-free both phases
    __shared__ float attns[H_][K_];
    __shared__ int idxs[K_];
    const float scale = 0.17677669529663687f;
    qs[t] = g_xq[(size_t)p*C_ + t] * scale;
    ks[t] = g_xk[(size_t)p*C_ + t];
    vs[t] = g_xv[(size_t)p*C_ + t];
    if (t < K_) idxs[t] = g_idx[p*K_ + t];
    __syncthreads();

    // coalesced gather of 32 neighbor rows (K and V): warp covers 32 consecutive ch
    #pragma unroll
    for (int e = t; e < K_*C_; e += 128) {
        int j = e >> 7, c = e & (C_-1);
        size_t base = ((size_t)(b*N_ + idxs[j]))*C_ + c;
        kn[j][c] = g_xk[base];
        vn[j][c] = g_xv[base];
    }
    __syncthreads();

    // energy: lane = neighbor
    float e = 0.f;
    #pragma unroll
    for (int d = 0; d < D_; d++)
        e += qs[h*D_ + d] * (kn[lane][h*D_ + d] - ks[h*D_ + d]);
    float mx = e;
    #pragma unroll
    for (int o = 16; o > 0; o >>= 1) mx = fmaxf(mx, __shfl_xor_sync(0xffffffffu, mx, o));
    float ex = __expf(e - mx);
    float sm = ex;
    #pragma unroll
    for (int o = 16; o > 0; o >>= 1) sm += __shfl_xor_sync(0xffffffffu, sm, o);
    attns[h][lane] = ex / sm;
    __syncwarp();

    // output: lane = dim
    float vself = vs[h*D_ + lane];
    float acc = 0.f;
    #pragma unroll
    for (int jj = 0; jj < K_; jj++)
        acc += attns[h][jj] * (vn[jj][h*D_ + lane] - vself);
    g_s1[(size_t)p*C_ + t] = x[(size_t)b*C_*N_ + (size_t)t*N_ + n] + acc;
}

// ---------------- BN stats ----------------
__global__ void bnstats_kernel(int which) {
    const float* src = which ? g_s2 : g_s1;
    float* sums      = which ? g_sum2 : g_sum1;
    int t = threadIdx.x;
    const float* base = src + (size_t)blockIdx.x*64*C_;
    float s = 0.f, ss = 0.f;
    #pragma unroll 8
    for (int q = 0; q < 64; q++) { float v = base[(size_t)q*C_ + t]; s += v; ss += v*v; }
    atomicAdd(&sums[t], s);
    atomicAdd(&sums[t + C_], ss);
}

__global__ void bnfin_kernel(int which) {
    const float* sums = which ? g_sum2 : g_sum1;
    float* stat       = which ? g_stat2 : g_stat1;
    int c = threadIdx.x;
    float m = sums[c] * (1.f/(float)P_);
    float var = sums[c + C_] * (1.f/(float)P_) - m*m;
    stat[c] = m;
    stat[c + C_] = rsqrtf(var + EPSbn);
}

// ---------------- x1 = BN(s1): straight + tiled transpose ----------------
__global__ void x1_kernel(const float* __restrict__ g1, const float* __restrict__ b1) {
    __shared__ float tile[32][33];
    int p0 = blockIdx.x*32;       // P_/32 blocks
    int c0 = blockIdx.y*32;       // C_/32
    int tx = threadIdx.x, ty = threadIdx.y;   // 32 x 8
    #pragma unroll
    for (int r = 0; r < 4; r++) {
        int pl = ty + r*8;
        int c = c0 + tx;
        float v = (g_s1[(size_t)(p0+pl)*C_ + c] - g_stat1[c]) * g_stat1[c + C_] * g1[c] + b1[c];
        g_x1[(size_t)(p0+pl)*C_ + c] = v;
        tile[pl][tx] = v;
    }
    __syncthreads();
    #pragma unroll
    for (int r = 0; r < 4; r++) {
        int cl = ty + r*8;
        g_x1T[(size_t)(c0+cl)*P_ + p0 + tx] = tile[tx][cl];
    }
}

// ---------------- final BN2 + transpose to [B,C,N] ----------------
__global__ void out_kernel(float* __restrict__ out,
                           const float* __restrict__ g2, const float* __restrict__ b2) {
    __shared__ float tile[32][33];
    int b = blockIdx.z;
    int n0 = blockIdx.x*32, c0 = blockIdx.y*32;
    int tx = threadIdx.x, ty = threadIdx.y;
    #pragma unroll
    for (int r = 0; r < 4; r++) {
        int nl = ty + r*8;
        int c = c0 + tx;
        float v = g_s2[(size_t)(b*N_ + n0 + nl)*C_ + c];
        v = (v - g_stat2[c]) * g_stat2[c + C_] * g2[c] + b2[c];
        tile[nl][tx] = v;
    }
    __syncthreads();
    #pragma unroll
    for (int r = 0; r < 4; r++) {
        int cl = ty + r*8;
        out[(size_t)b*C_*N_ + (size_t)(c0 + cl)*N_ + n0 + tx] = tile[tx][cl];
    }
}

// ---------------- launch ----------------
extern "C" void kernel_launch(void* const* d_in, const int* in_sizes, int n_in,
                              void* d_out, int out_size) {
    const float* x  = (const float*)d_in[0];
    const float* wq = (const float*)d_in[1];
    const float* wk = (const float*)d_in[2];
    const float* wv = (const float*)d_in[3];
    const float* w1 = (const float*)d_in[4];
    const float* w2 = (const float*)d_in[5];
    const float* g1 = (const float*)d_in[6];
    const float* b1 = (const float*)d_in[7];
    const float* g2 = (const float*)d_in[8];
    const float* b2 = (const float*)d_in[9];
    float* out = (float*)d_out;

    void *pwqkv, *pw1, *pw2;
    cudaGetSymbolAddress(&pwqkv, g_wqkvT);
    cudaGetSymbolAddress(&pw1, g_w1T);
    cudaGetSymbolAddress(&pw2, g_w2T);

    init_kernel<<<1, 256>>>();
    colnorm_kernel<<<P_/256, 256>>>(x);
    tpf_kernel<<<(C_*C_)/256, 256>>>(wq, (float*)pwqkv, C_, C_, 384, 0);
    tpf_kernel<<<(C_*C_)/256, 256>>>(wk, (float*)pwqkv, C_, C_, 384, 128);
    tpf_kernel<<<(C_*C_)/256, 256>>>(wv, (float*)pwqkv, C_, C_, 384, 256);
    tpf_kernel<<<(F_*C_)/256, 256>>>(w1, (float*)pw1, F_, C_, F_, 0);
    tpf_kernel<<<(C_*F_)/256, 256>>>(w2, (float*)pw2, C_, F_, C_, 0);

    score_sgemm<<<dim3(136, 1, B_), 256>>>(x);
    topk_kernel<<<P_, 256>>>();
    proj_sgemm<<<dim3(3, N_/128, B_), 256>>>(x);
    attn_kernel<<<P_, 128>>>(x);

    bnstats_kernel<<<P_/64, 128>>>(0);
    bnfin_kernel<<<1, 128>>>(0);
    x1_kernel<<<dim3(P_/32, C_/32), dim3(32, 8)>>>(g1, b1);

    ffn1_sgemm<<<dim3(F_/128, P_/128), 256>>>();
    ffn2_sgemm<<<dim3(1, P_/128), 256>>>();

    bnstats_kernel<<<P_/64, 128>>>(1);
    bnfin_kernel<<<1, 128>>>(1);

    out_kernel<<<dim3(N_/32, C_/32, B_), dim3(32, 8)>>>(out, g2, b2);
}

// round 8
// speedup vs baseline: 1.8034x; 1.0984x over previous
#include <cuda_runtime.h>
#include <math.h>

#define B_ 8
#define C_ 128
#define N_ 2048
#define H_ 4
#define K_ 32
#define D_ 32
#define F_ 512
#define P_ (B_*N_)
#define EPSbn 1e-5f

// ---------------- scratch (static device allocations only) ----------------
__device__ float g_S[B_*N_*N_];        // 128MB scores; later reused as hT [o][p] for FFN
__device__ int   g_idx[P_*K_];
__device__ float g_xq[P_*C_];
__device__ float g_xk[P_*C_];
__device__ float g_xv[P_*C_];
__device__ float g_x2[P_];
__device__ float g_s1[P_*C_];
__device__ float g_x1[P_*C_];          // [p][c]
__device__ float g_x1T[C_*P_];         // [c][p]
__device__ float g_s2[P_*C_];
__device__ float g_sum1[2*C_];
__device__ float g_sum2[2*C_];
__device__ float g_stat1[2*C_];
__device__ float g_stat2[2*C_];
__device__ float g_wqkvT[C_*384];      // [cin][3*cout]
__device__ float g_w1T[C_*F_];         // [cin][o]
__device__ float g_w2T[F_*C_];         // [o][cout]

// ---------------- fused prep: zero BN sums + transpose all weights ----------
__global__ void prep_kernel(const float* __restrict__ wq, const float* __restrict__ wk,
                            const float* __restrict__ wv, const float* __restrict__ w1,
                            const float* __restrict__ w2) {
    int i = blockIdx.x*256 + threadIdx.x;
    if (i < 2*C_) { g_sum1[i] = 0.f; g_sum2[i] = 0.f; }
    if (i < 16384) {
        int r = i / C_, c = i % C_;
        g_wqkvT[c*384 + r] = wq[i];
    } else if (i < 32768) {
        int j = i - 16384; int r = j / C_, c = j % C_;
        g_wqkvT[c*384 + 128 + r] = wk[j];
    } else if (i < 49152) {
        int j = i - 32768; int r = j / C_, c = j % C_;
        g_wqkvT[c*384 + 256 + r] = wv[j];
    } else if (i < 114688) {
        int j = i - 49152; int r = j / C_, c = j % C_;     // w1: [F_][C_]
        g_w1T[(size_t)c*F_ + r] = w1[j];
    } else if (i < 180224) {
        int j = i - 114688; int r = j / F_, c = j % F_;    // w2: [C_][F_]
        g_w2T[(size_t)c*C_ + r] = w2[j];
    }
}

// ---------------- per-point squared norms ----------------
__global__ void colnorm_kernel(const float* __restrict__ x) {
    int p = blockIdx.x*blockDim.x + threadIdx.x;
    if (p >= P_) return;
    int b = p / N_, n = p % N_;
    const float* xb = x + (size_t)b*C_*N_ + n;
    float s = 0.f;
    #pragma unroll
    for (int c = 0; c < C_; c++) { float v = xb[(size_t)c*N_]; s += v*v; }
    g_x2[p] = s;
}

// ---------- double-buffered SGEMM mainloop: 128x128 tile, 8x8 micro, BK=8 ----
// One __syncthreads per chunk; next chunk prefetched to regs during compute.
__device__ __forceinline__ void sgemm_body(
    const float* __restrict__ Ag, long sA,
    const float* __restrict__ Bg, long sB,
    int KD, float acc[8][8],
    float (*As)[8][128], float (*Bs)[8][128], int t)
{
    int tx = t & 15, ty = t >> 4;
    int kk = t >> 5, mm = (t*4) & 127;
    // preload chunk 0
    {
        float4 a0 = *(const float4*)&Ag[(long)kk*sA + mm];
        float4 b0 = *(const float4*)&Bg[(long)kk*sB + mm];
        *(float4*)&As[0][kk][mm] = a0;
        *(float4*)&Bs[0][kk][mm] = b0;
    }
    __syncthreads();
    int nc = KD >> 3;
    for (int c = 0; c < nc; c++) {
        float4 an, bn;
        bool more = (c + 1 < nc);
        if (more) {
            long ko = (long)((c + 1)*8 + kk);
            an = *(const float4*)&Ag[ko*sA + mm];
            bn = *(const float4*)&Bg[ko*sB + mm];
        }
        int cur = c & 1;
        #pragma unroll
        for (int k = 0; k < 8; k++) {
            float a[8], b[8];
            *(float4*)(a)   = *(float4*)&As[cur][k][ty*8];
            *(float4*)(a+4) = *(float4*)&As[cur][k][ty*8+4];
            *(float4*)(b)   = *(float4*)&Bs[cur][k][tx*8];
            *(float4*)(b+4) = *(float4*)&Bs[cur][k][tx*8+4];
            #pragma unroll
            for (int iy = 0; iy < 8; iy++)
                #pragma unroll
                for (int ix = 0; ix < 8; ix++) acc[iy][ix] += a[iy]*b[ix];
        }
        if (more) {
            int nxt = cur ^ 1;
            *(float4*)&As[nxt][kk][mm] = an;
            *(float4*)&Bs[nxt][kk][mm] = bn;
            __syncthreads();
        }
    }
}

#define ACC_INIT float acc[8][8];                                   \
    _Pragma("unroll") for (int iy = 0; iy < 8; iy++)                \
    _Pragma("unroll") for (int ix = 0; ix < 8; ix++) acc[iy][ix] = 0.f;

// ---------------- score: S[n,m] = dot(x_n,x_m) - 0.5||x_m||^2, symmetric -----
__global__ __launch_bounds__(256) void score_sgemm(const float* __restrict__ x) {
    const int T = 16;
    int L = blockIdx.x;
    int i = 0, rem = L;
    while (rem >= T - i) { rem -= (T - i); i++; }
    int j = i + rem;
    int n0 = i*128, m0 = j*128;
    int b = blockIdx.z;
    const float* xb  = x + (size_t)b*C_*N_;
    float* Sb        = g_S + (size_t)b*N_*N_;
    const float* x2b = g_x2 + b*N_;

    __shared__ float As[2][8][128], Bs[2][8][128];
    __shared__ float sbuf[16][132];
    int t = threadIdx.x, tx = t & 15, ty = t >> 4;
    ACC_INIT
    sgemm_body(xb + n0, N_, xb + m0, N_, C_, acc, As, Bs, t);

    int r0 = n0 + ty*8, c0 = m0 + tx*8;
    float x2r[8], x2c[8];
    #pragma unroll
    for (int q = 0; q < 8; q++) { x2r[q] = x2b[r0+q]; x2c[q] = 0.5f*x2b[c0+q]; }
    #pragma unroll
    for (int iy = 0; iy < 8; iy++) {
        float* row = &Sb[(size_t)(r0+iy)*N_ + c0];
        *(float4*)(row)   = make_float4(acc[iy][0]-x2c[0], acc[iy][1]-x2c[1],
                                        acc[iy][2]-x2c[2], acc[iy][3]-x2c[3]);
        *(float4*)(row+4) = make_float4(acc[iy][4]-x2c[4], acc[iy][5]-x2c[5],
                                        acc[iy][6]-x2c[6], acc[iy][7]-x2c[7]);
    }
    if (i != j) {
        int lr = t >> 4, lc = (t & 15)*8;
        #pragma unroll
        for (int ix = 0; ix < 8; ix++) {
            __syncthreads();
            #pragma unroll
            for (int iy = 0; iy < 8; iy++)
                sbuf[tx][ty*8 + iy] = acc[iy][ix] - 0.5f*x2r[iy];
            __syncthreads();
            float* dst = &Sb[(size_t)(m0 + lr*8 + ix)*N_ + n0 + lc];
            *(float4*)(dst)   = make_float4(sbuf[lr][lc],   sbuf[lr][lc+1],
                                            sbuf[lr][lc+2], sbuf[lr][lc+3]);
            *(float4*)(dst+4) = make_float4(sbuf[lr][lc+4], sbuf[lr][lc+5],
                                            sbuf[lr][lc+6], sbuf[lr][lc+7]);
        }
    }
}

// ---------------- fused q/k/v projection ----------------
__global__ __launch_bounds__(256) void proj_sgemm(const float* __restrict__ x) {
    int widx = blockIdx.x;
    int n0 = blockIdx.y*128;
    int b = blockIdx.z;
    const float* xb = x + (size_t)b*C_*N_;
    float* outp = (widx == 0 ? g_xq : widx == 1 ? g_xk : g_xv) + (size_t)b*N_*C_;

    __shared__ float As[2][8][128], Bs[2][8][128];
    int t = threadIdx.x, tx = t & 15, ty = t >> 4;
    ACC_INIT
    sgemm_body(xb + n0, N_, g_wqkvT + widx*128, 384, C_, acc, As, Bs, t);

    #pragma unroll
    for (int iy = 0; iy < 8; iy++) {
        int r = n0 + ty*8 + iy;
        float* row = &outp[(size_t)r*C_ + tx*8];
        *(float4*)(row)   = make_float4(acc[iy][0], acc[iy][1], acc[iy][2], acc[iy][3]);
        *(float4*)(row+4) = make_float4(acc[iy][4], acc[iy][5], acc[iy][6], acc[iy][7]);
    }
}

// ---------------- ffn1: hT[o][p] = leaky(sum_c x1T[c][p] * w1T[c][o]) ---------
__global__ __launch_bounds__(256) void ffn1_sgemm() {
    int o0 = blockIdx.x*128;
    int p0 = blockIdx.y*128;
    float* hT = g_S;

    __shared__ float As[2][8][128], Bs[2][8][128];
    int t = threadIdx.x, tx = t & 15, ty = t >> 4;
    ACC_INIT
    sgemm_body(g_x1T + p0, P_, g_w1T + o0, F_, C_, acc, As, Bs, t);

    #pragma unroll
    for (int ix = 0; ix < 8; ix++) {
        int col = o0 + tx*8 + ix;
        float v[8];
        #pragma unroll
        for (int iy = 0; iy < 8; iy++) {
            float u = acc[iy][ix];
            v[iy] = u > 0.f ? u : 0.2f*u;
        }
        float* cp = &hT[(size_t)col*P_ + p0 + ty*8];
        *(float4*)(cp)   = make_float4(v[0], v[1], v[2], v[3]);
        *(float4*)(cp+4) = make_float4(v[4], v[5], v[6], v[7]);
    }
}

// ---------------- ffn2: s2[p][c] = x1[p][c] + sum_o hT[o][p] * w2T[o][c] ------
__global__ __launch_bounds__(256) void ffn2_sgemm() {
    int p0 = blockIdx.y*128;
    const float* hT = g_S;

    __shared__ float As[2][8][128], Bs[2][8][128];
    int t = threadIdx.x, tx = t & 15, ty = t >> 4;
    ACC_INIT
    sgemm_body(hT + p0, P_, g_w2T, C_, F_, acc, As, Bs, t);

    #pragma unroll
    for (int iy = 0; iy < 8; iy++) {
        int r = p0 + ty*8 + iy;
        const float* resp = &g_x1[(size_t)r*C_ + tx*8];
        float* op = &g_s2[(size_t)r*C_ + tx*8];
        float4 e0 = *(const float4*)(resp);
        float4 e1 = *(const float4*)(resp+4);
        *(float4*)(op)   = make_float4(acc[iy][0]+e0.x, acc[iy][1]+e0.y,
                                       acc[iy][2]+e0.z, acc[iy][3]+e0.w);
        *(float4*)(op+4) = make_float4(acc[iy][4]+e1.x, acc[iy][5]+e1.y,
                                       acc[iy][6]+e1.z, acc[iy][7]+e1.w);
    }
}

// ---------------- top-32 per row: exact 4-pass radix select ----------------
__global__ __launch_bounds__(256) void topk_kernel() {
    int row = blockIdx.x;
    const float* Srow = g_S + (size_t)row*N_;
    int t = threadIdx.x;
    unsigned u[8];
    #pragma unroll
    for (int q = 0; q < 8; q++) {
        unsigned b = __float_as_uint(Srow[t + q*256]);
        u[q] = (b & 0x80000000u) ? ~b : (b | 0x80000000u);
    }
    __shared__ unsigned hist[256];
    __shared__ unsigned suffix[256];
    __shared__ unsigned wsum[8];
    __shared__ unsigned sh_prefix;
    __shared__ int sh_need, sh_cnt, sh_eqcnt;
    __shared__ int eqbuf[256];
    if (t == 0) { sh_prefix = 0u; sh_need = K_; }
    int lane = t & 31, wid = t >> 5;

    #pragma unroll
    for (int pass = 0; pass < 4; pass++) {
        int shift = 24 - pass*8;
        hist[t] = 0u;
        __syncthreads();
        unsigned pref = sh_prefix;
        int need = sh_need;
        unsigned mask = (pass == 0) ? 0u : (0xFFFFFFFFu << (shift + 8));
        #pragma unroll
        for (int q = 0; q < 8; q++)
            if ((u[q] & mask) == pref)
                atomicAdd(&hist[(u[q] >> shift) & 255u], 1u);
        __syncthreads();
        int r = 255 - t;
        unsigned val = hist[r];
        #pragma unroll
        for (int o = 1; o < 32; o <<= 1) {
            unsigned up = __shfl_up_sync(0xffffffffu, val, o);
            if (lane >= o) val += up;
        }
        if (lane == 31) wsum[wid] = val;
        __syncthreads();
        #pragma unroll
        for (int w = 0; w < 8; w++) if (w < wid) val += wsum[w];
        suffix[r] = val;
        __syncthreads();
        unsigned nxt = (r == 255) ? 0u : suffix[r + 1];
        if (suffix[r] >= (unsigned)need && nxt < (unsigned)need) {
            sh_prefix = pref | ((unsigned)r << shift);
            sh_need = need - (int)nxt;
        }
        __syncthreads();
    }

    unsigned T = sh_prefix;
    int need_eq = sh_need;
    if (t == 0) { sh_cnt = 0; sh_eqcnt = 0; }
    __syncthreads();
    int* outp = g_idx + row*K_;
    #pragma unroll
    for (int q = 0; q < 8; q++) {
        if (u[q] > T) {
            int pos = atomicAdd(&sh_cnt, 1);
            outp[pos] = t + q*256;
        } else if (u[q] == T) {
            int e = atomicAdd(&sh_eqcnt, 1);
            if (e < 256) eqbuf[e] = t + q*256;
        }
    }
    __syncthreads();
    if (t == 0) {
        int cnt = sh_cnt;
        int m = sh_eqcnt; if (m > 256) m = 256;
        for (int i = 0; i < need_eq; i++) {
            int best = 0x7fffffff, bj = -1;
            for (int j = 0; j < m; j++)
                if (eqbuf[j] < best) { best = eqbuf[j]; bj = j; }
            eqbuf[bj] = 0x7fffffff;
            outp[cnt + i] = best;
        }
    }
}

// ---------------- attention: smem-staged neighbor K/V (coalesced gather) ------
__global__ __launch_bounds__(128) void attn_kernel(const float* __restrict__ x) {
    int p = blockIdx.x;
    int b = p >> 11, n = p & (N_-1);
    int t = threadIdx.x;
    int h = t >> 5, lane = t & 31;
    __shared__ float qs[C_], ks[C_], vs[C_];
    __shared__ float kn[K_][C_+1], vn[K_][C_+1];
    __shared__ float attns[H_][K_];
    __shared__ int idxs[K_];
    const float scale = 0.17677669529663687f;
    qs[t] = g_xq[(size_t)p*C_ + t] * scale;
    ks[t] = g_xk[(size_t)p*C_ + t];
    vs[t] = g_xv[(size_t)p*C_ + t];
    if (t < K_) idxs[t] = g_idx[p*K_ + t];
    __syncthreads();

    #pragma unroll
    for (int e = t; e < K_*C_; e += 128) {
        int j = e >> 7, c = e & (C_-1);
        size_t base = ((size_t)(b*N_ + idxs[j]))*C_ + c;
        kn[j][c] = g_xk[base];
        vn[j][c] = g_xv[base];
    }
    __syncthreads();

    float e = 0.f;
    #pragma unroll
    for (int d = 0; d < D_; d++)
        e += qs[h*D_ + d] * (kn[lane][h*D_ + d] - ks[h*D_ + d]);
    float mx = e;
    #pragma unroll
    for (int o = 16; o > 0; o >>= 1) mx = fmaxf(mx, __shfl_xor_sync(0xffffffffu, mx, o));
    float ex = __expf(e - mx);
    float sm = ex;
    #pragma unroll
    for (int o = 16; o > 0; o >>= 1) sm += __shfl_xor_sync(0xffffffffu, sm, o);
    attns[h][lane] = ex / sm;
    __syncwarp();

    float vself = vs[h*D_ + lane];
    float acc = 0.f;
    #pragma unroll
    for (int jj = 0; jj < K_; jj++)
        acc += attns[h][jj] * (vn[jj][h*D_ + lane] - vself);
    g_s1[(size_t)p*C_ + t] = x[(size_t)b*C_*N_ + (size_t)t*N_ + n] + acc;
}

// ---------------- BN stats ----------------
__global__ void bnstats_kernel(int which) {
    const float* src = which ? g_s2 : g_s1;
    float* sums      = which ? g_sum2 : g_sum1;
    int t = threadIdx.x;
    const float* base = src + (size_t)blockIdx.x*64*C_;
    float s = 0.f, ss = 0.f;
    #pragma unroll 8
    for (int q = 0; q < 64; q++) { float v = base[(size_t)q*C_ + t]; s += v; ss += v*v; }
    atomicAdd(&sums[t], s);
    atomicAdd(&sums[t + C_], ss);
}

__global__ void bnfin_kernel(int which) {
    const float* sums = which ? g_sum2 : g_sum1;
    float* stat       = which ? g_stat2 : g_stat1;
    int c = threadIdx.x;
    float m = sums[c] * (1.f/(float)P_);
    float var = sums[c + C_] * (1.f/(float)P_) - m*m;
    stat[c] = m;
    stat[c + C_] = rsqrtf(var + EPSbn);
}

// ---------------- x1 = BN(s1): straight + tiled transpose ----------------
__global__ void x1_kernel(const float* __restrict__ g1, const float* __restrict__ b1) {
    __shared__ float tile[32][33];
    int p0 = blockIdx.x*32;
    int c0 = blockIdx.y*32;
    int tx = threadIdx.x, ty = threadIdx.y;
    #pragma unroll
    for (int r = 0; r < 4; r++) {
        int pl = ty + r*8;
        int c = c0 + tx;
        float v = (g_s1[(size_t)(p0+pl)*C_ + c] - g_stat1[c]) * g_stat1[c + C_] * g1[c] + b1[c];
        g_x1[(size_t)(p0+pl)*C_ + c] = v;
        tile[pl][tx] = v;
    }
    __syncthreads();
    #pragma unroll
    for (int r = 0; r < 4; r++) {
        int cl = ty + r*8;
        g_x1T[(size_t)(c0+cl)*P_ + p0 + tx] = tile[tx][cl];
    }
}

// ---------------- final BN2 + transpose to [B,C,N] ----------------
__global__ void out_kernel(float* __restrict__ out,
                           const float* __restrict__ g2, const float* __restrict__ b2) {
    __shared__ float tile[32][33];
    int b = blockIdx.z;
    int n0 = blockIdx.x*32, c0 = blockIdx.y*32;
    int tx = threadIdx.x, ty = threadIdx.y;
    #pragma unroll
    for (int r = 0; r < 4; r++) {
        int nl = ty + r*8;
        int c = c0 + tx;
        float v = g_s2[(size_t)(b*N_ + n0 + nl)*C_ + c];
        v = (v - g_stat2[c]) * g_stat2[c + C_] * g2[c] + b2[c];
        tile[nl][tx] = v;
    }
    __syncthreads();
    #pragma unroll
    for (int r = 0; r < 4; r++) {
        int cl = ty + r*8;
        out[(size_t)b*C_*N_ + (size_t)(c0 + cl)*N_ + n0 + tx] = tile[tx][cl];
    }
}

// ---------------- launch ----------------
extern "C" void kernel_launch(void* const* d_in, const int* in_sizes, int n_in,
                              void* d_out, int out_size) {
    const float* x  = (const float*)d_in[0];
    const float* wq = (const float*)d_in[1];
    const float* wk = (const float*)d_in[2];
    const float* wv = (const float*)d_in[3];
    const float* w1 = (const float*)d_in[4];
    const float* w2 = (const float*)d_in[5];
    const float* g1 = (const float*)d_in[6];
    const float* b1 = (const float*)d_in[7];
    const float* g2 = (const float*)d_in[8];
    const float* b2 = (const float*)d_in[9];
    float* out = (float*)d_out;

    prep_kernel<<<704, 256>>>(wq, wk, wv, w1, w2);
    colnorm_kernel<<<P_/256, 256>>>(x);

    score_sgemm<<<dim3(136, 1, B_), 256>>>(x);
    topk_kernel<<<P_, 256>>>();
    proj_sgemm<<<dim3(3, N_/128, B_), 256>>>(x);
    attn_kernel<<<P_, 128>>>(x);

    bnstats_kernel<<<P_/64, 128>>>(0);
    bnfin_kernel<<<1, 128>>>(0);
    x1_kernel<<<dim3(P_/32, C_/32), dim3(32, 8)>>>(g1, b1);

    ffn1_sgemm<<<dim3(F_/128, P_/128), 256>>>();
    ffn2_sgemm<<<dim3(1, P_/128), 256>>>();

    bnstats_kernel<<<P_/64, 128>>>(1);
    bnfin_kernel<<<1, 128>>>(1);

    out_kernel<<<dim3(N_/32, C_/32, B_), dim3(32, 8)>>>(out, g2, b2);
}